// round 11
// baseline (speedup 1.0000x reference)
#include <cuda_runtime.h>
#include <cuda_bf16.h>
#include <math.h>

// Problem constants
#define B_SZ   1024
#define LU     200
#define LH     50
#define D_SZ   768
#define XCOLS  1552      // 768 + 768 + 16
#define HID    512
#define KQ     388       // split-K quarter
#define KT4    97        // 388 / 4 k-tiles (BK=4)

// -------- scratch (device globals; no allocation allowed) --------
__device__ __align__(16) float g_x[B_SZ * XCOLS];     // concatenated input to fc1
__device__ __align__(16) float g_y[B_SZ * HID];       // fc1 output (pre-BN)
__device__ __align__(16) float g_p[4][B_SZ * HID];    // GEMM partials (split-K=4)
__device__ float g_sum[HID];                          // column sums
__device__ float g_sum2[HID];                         // column sums of squares

// =====================================================================
// Kernel 1: masked mean over [B, L, 768] -> g_x columns [off, off+768)
// grid: (1024, 2)  block: 192 threads (192 * float4 = 768 cols)
// 8-deep unroll for MLP=8.
// =====================================================================
__global__ void masked_mean_kernel(const float* __restrict__ uf,
                                   const int*   __restrict__ ul,
                                   const float* __restrict__ hf,
                                   const int*   __restrict__ hl)
{
    int b = blockIdx.x;
    int t = threadIdx.x;

    const float4* base;
    int len, off;
    if (blockIdx.y == 0) {
        base = (const float4*)(uf + (size_t)b * LU * D_SZ);
        len  = ul[b];
        off  = 0;
    } else {
        base = (const float4*)(hf + (size_t)b * LH * D_SZ);
        len  = hl[b];
        off  = 768;
    }

    float4 s0 = make_float4(0.f, 0.f, 0.f, 0.f);
    float4 s1 = s0, s2 = s0, s3 = s0;
    float4 s4 = s0, s5 = s0, s6 = s0, s7 = s0;

    int l = 0;
    for (; l + 8 <= len; l += 8) {
        float4 v0 = base[(size_t)(l + 0) * 192 + t];
        float4 v1 = base[(size_t)(l + 1) * 192 + t];
        float4 v2 = base[(size_t)(l + 2) * 192 + t];
        float4 v3 = base[(size_t)(l + 3) * 192 + t];
        float4 v4 = base[(size_t)(l + 4) * 192 + t];
        float4 v5 = base[(size_t)(l + 5) * 192 + t];
        float4 v6 = base[(size_t)(l + 6) * 192 + t];
        float4 v7 = base[(size_t)(l + 7) * 192 + t];
        s0.x += v0.x; s0.y += v0.y; s0.z += v0.z; s0.w += v0.w;
        s1.x += v1.x; s1.y += v1.y; s1.z += v1.z; s1.w += v1.w;
        s2.x += v2.x; s2.y += v2.y; s2.z += v2.z; s2.w += v2.w;
        s3.x += v3.x; s3.y += v3.y; s3.z += v3.z; s3.w += v3.w;
        s4.x += v4.x; s4.y += v4.y; s4.z += v4.z; s4.w += v4.w;
        s5.x += v5.x; s5.y += v5.y; s5.z += v5.z; s5.w += v5.w;
        s6.x += v6.x; s6.y += v6.y; s6.z += v6.z; s6.w += v6.w;
        s7.x += v7.x; s7.y += v7.y; s7.z += v7.z; s7.w += v7.w;
    }
    for (; l < len; l++) {
        float4 v = base[(size_t)l * 192 + t];
        s0.x += v.x; s0.y += v.y; s0.z += v.z; s0.w += v.w;
    }

    float inv = 1.0f / (float)len;
    float4 r;
    r.x = (((s0.x + s1.x) + (s2.x + s3.x)) + ((s4.x + s5.x) + (s6.x + s7.x))) * inv;
    r.y = (((s0.y + s1.y) + (s2.y + s3.y)) + ((s4.y + s5.y) + (s6.y + s7.y))) * inv;
    r.z = (((s0.z + s1.z) + (s2.z + s3.z)) + ((s4.z + s5.z) + (s6.z + s7.z))) * inv;
    r.w = (((s0.w + s1.w) + (s2.w + s3.w)) + ((s4.w + s5.w) + (s6.w + s7.w))) * inv;

    *(float4*)(g_x + (size_t)b * XCOLS + off + t * 4) = r;
}

// =====================================================================
// Kernel 2: NeuMF interaction vector -> g_x columns [1536, 1552)
// Also zeroes g_sum / g_sum2 for this replay (block 0).
// grid: 8 blocks x 128 threads (1 thread per batch row)
// =====================================================================
__global__ void ncf_kernel(const int* __restrict__ users, const int* __restrict__ items,
                           const float* __restrict__ u_mf,  const float* __restrict__ i_mf,
                           const float* __restrict__ u_mlp, const float* __restrict__ i_mlp,
                           const float* __restrict__ w0, const float* __restrict__ b0,
                           const float* __restrict__ w1, const float* __restrict__ b1,
                           const float* __restrict__ w2, const float* __restrict__ b2)
{
    __shared__ float sw0[16 * 32], sb0[32];
    __shared__ float sw1[32 * 16], sb1[16];
    __shared__ float sw2[16 * 8],  sb2[8];

    int t = threadIdx.x;

    if (blockIdx.x == 0) {
        #pragma unroll
        for (int i = 0; i < 4; i++) {
            g_sum [t + i * 128] = 0.f;
            g_sum2[t + i * 128] = 0.f;
        }
    }

    for (int i = t; i < 512; i += 128) sw0[i] = w0[i];
    for (int i = t; i < 512; i += 128) sw1[i] = w1[i];
    if (t < 128) sw2[t] = w2[t];
    if (t < 32)  sb0[t] = b0[t];
    if (t < 16)  sb1[t] = b1[t];
    if (t < 8)   sb2[t] = b2[t];
    __syncthreads();

    int b = blockIdx.x * 128 + t;
    int u = users[b];
    int it = items[b];

    float in16[16];
    #pragma unroll
    for (int j = 0; j < 8; j++) in16[j]     = u_mlp[u * 8 + j];
    #pragma unroll
    for (int j = 0; j < 8; j++) in16[8 + j] = i_mlp[it * 8 + j];

    float h1[32];
    #pragma unroll
    for (int j = 0; j < 32; j++) {
        float s = sb0[j];
        #pragma unroll
        for (int k = 0; k < 16; k++) s += in16[k] * sw0[k * 32 + j];
        h1[j] = fmaxf(s, 0.f);
    }
    float h2[16];
    #pragma unroll
    for (int j = 0; j < 16; j++) {
        float s = sb1[j];
        #pragma unroll
        for (int k = 0; k < 32; k++) s += h1[k] * sw1[k * 16 + j];
        h2[j] = fmaxf(s, 0.f);
    }
    float* xp = g_x + (size_t)b * XCOLS + 1536;
    #pragma unroll
    for (int j = 0; j < 8; j++) {
        float s = sb2[j];
        #pragma unroll
        for (int k = 0; k < 16; k++) s += h2[k] * sw2[k * 8 + j];
        xp[j] = fmaxf(s, 0.f);
    }
    #pragma unroll
    for (int j = 0; j < 8; j++) {
        xp[8 + j] = u_mf[u * 8 + j] * i_mf[it * 8 + j];
    }
}

// =====================================================================
// Kernel 3: fc1 GEMM, split-K=4.
//   g_p[z][1024,512] = g_x[:, z*388:(z+1)*388] @ W[z*388:(z+1)*388, :]
// Block tile 32(M) x 128(N), BK=4, 64 threads, 8x8 micro-tile.
// grid: (32, 4, 4) = 512 blocks, 1024 warps -> 1.73 warps/SMSP.
// =====================================================================
__global__ void __launch_bounds__(64) fc1_gemm_kernel(const float* __restrict__ W)
{
    __shared__ __align__(16) float As[4][36];   // [k][m], padded row
    __shared__ __align__(16) float Bs[4][128];  // [k][n]

    int t  = threadIdx.x;
    int m0 = blockIdx.x * 32;
    int n0 = blockIdx.y * 128;
    int k0 = blockIdx.z * KQ;

    // A loaders: threads 0..31, one float4 covering k 0..3 of row t
    bool aload = (t < 32);
    // B loaders: all 64 threads: row b_k (0..3), cols b_n and b_n+64
    int b_k = t >> 4;             // 0..3
    int b_n = (t & 15) * 4;       // 0..60

    const float* gA = g_x + (size_t)(m0 + t) * XCOLS + k0;
    const float* gB = W + (size_t)(k0 + b_k) * HID + n0 + b_n;

    float4 pa  = aload ? *(const float4*)gA : make_float4(0.f,0.f,0.f,0.f);
    float4 pb0 = *(const float4*)gB;
    float4 pb1 = *(const float4*)(gB + 64);

    int tm = t & 3;   // row group: rows tm*8 .. tm*8+7
    int tn = t >> 2;  // col group: cols tn*8 .. tn*8+7  (0..15)

    unsigned long long acc[8][4] = {};  // [m][n-pair] packed f32x2

    for (int kt = 0; kt < KT4; kt++) {
        __syncthreads();
        if (aload) {
            As[0][t] = pa.x;
            As[1][t] = pa.y;
            As[2][t] = pa.z;
            As[3][t] = pa.w;
        }
        *(float4*)&Bs[b_k][b_n]      = pb0;
        *(float4*)&Bs[b_k][b_n + 64] = pb1;
        __syncthreads();

        if (kt + 1 < KT4) {
            const float* nB = gB + (size_t)(kt + 1) * 4 * HID;
            if (aload) pa = *(const float4*)(gA + (size_t)(kt + 1) * 4);
            pb0 = *(const float4*)nB;
            pb1 = *(const float4*)(nB + 64);
        }

        #pragma unroll
        for (int k = 0; k < 4; k++) {
            ulonglong2 b01 = *(const ulonglong2*)&Bs[k][tn * 8];
            ulonglong2 b23 = *(const ulonglong2*)&Bs[k][tn * 8 + 4];
            float4 a0 = *(const float4*)&As[k][tm * 8];
            float4 a1 = *(const float4*)&As[k][tm * 8 + 4];
            float am[8] = {a0.x, a0.y, a0.z, a0.w, a1.x, a1.y, a1.z, a1.w};
            #pragma unroll
            for (int m = 0; m < 8; m++) {
                unsigned int av = __float_as_uint(am[m]);
                unsigned long long ad;
                asm("mov.b64 %0, {%1, %1};" : "=l"(ad) : "r"(av));
                asm("fma.rn.f32x2 %0, %1, %2, %0;" : "+l"(acc[m][0]) : "l"(ad), "l"(b01.x));
                asm("fma.rn.f32x2 %0, %1, %2, %0;" : "+l"(acc[m][1]) : "l"(ad), "l"(b01.y));
                asm("fma.rn.f32x2 %0, %1, %2, %0;" : "+l"(acc[m][2]) : "l"(ad), "l"(b23.x));
                asm("fma.rn.f32x2 %0, %1, %2, %0;" : "+l"(acc[m][3]) : "l"(ad), "l"(b23.y));
            }
        }
    }

    float* outp = g_p[blockIdx.z];
    #pragma unroll
    for (int m = 0; m < 8; m++) {
        int row = m0 + tm * 8 + m;
        int col = n0 + tn * 8;
        float4 v0, v1;
        v0.x = __uint_as_float((unsigned int)(acc[m][0]));
        v0.y = __uint_as_float((unsigned int)(acc[m][0] >> 32));
        v0.z = __uint_as_float((unsigned int)(acc[m][1]));
        v0.w = __uint_as_float((unsigned int)(acc[m][1] >> 32));
        v1.x = __uint_as_float((unsigned int)(acc[m][2]));
        v1.y = __uint_as_float((unsigned int)(acc[m][2] >> 32));
        v1.z = __uint_as_float((unsigned int)(acc[m][3]));
        v1.w = __uint_as_float((unsigned int)(acc[m][3] >> 32));
        *(float4*)(outp + (size_t)row * HID + col)     = v0;
        *(float4*)(outp + (size_t)row * HID + col + 4) = v1;
    }
}

// =====================================================================
// Kernel 4: combine split-K partials + bias, write g_y, accumulate
// per-column sums for BN (atomics; zeroed in ncf_kernel).
// grid: 128 blocks x 512 threads (thread = column), 8 rows per block
// =====================================================================
__global__ void bn_combine_kernel(const float* __restrict__ bias)
{
    int c  = threadIdx.x;
    int r0 = blockIdx.x * 8;
    float bs = bias[c];

    float s = 0.f, s2 = 0.f;
    #pragma unroll
    for (int i = 0; i < 8; i++) {
        size_t idx = (size_t)(r0 + i) * HID + c;
        float v = ((g_p[0][idx] + g_p[1][idx]) + (g_p[2][idx] + g_p[3][idx])) + bs;
        g_y[idx] = v;
        s  += v;
        s2 += v * v;
    }
    atomicAdd(&g_sum[c],  s);
    atomicAdd(&g_sum2[c], s2);
}

// =====================================================================
// Kernel 5: out[b] = sigmoid( relu(y*a + c) . fc3_w + fc3_b )
// Per-block: compute BN affine (a,c) into smem from g_sum/g_sum2,
// then 1 warp per batch row.
// grid: 128 blocks x 256 threads
// =====================================================================
__global__ void final_kernel(const float* __restrict__ gamma,
                             const float* __restrict__ beta,
                             const float* __restrict__ fc3_w,
                             const float* __restrict__ fc3_b,
                             float* __restrict__ out)
{
    __shared__ float sa[HID];
    __shared__ float sc[HID];

    int t = threadIdx.x;
    #pragma unroll
    for (int i = 0; i < 2; i++) {
        int ch = t + i * 256;
        float s1 = g_sum[ch];
        float s2 = g_sum2[ch];
        float m   = s1 * (1.0f / (float)B_SZ);
        float var = s2 * (1.0f / (float)B_SZ) - m * m;
        float a   = gamma[ch] * rsqrtf(var + 1e-5f);
        sa[ch] = a;
        sc[ch] = beta[ch] - m * a;
    }
    __syncthreads();

    int warp = t >> 5;
    int lane = t & 31;
    int b = blockIdx.x * 8 + warp;

    const float* yrow = g_y + (size_t)b * HID;
    float s = 0.f;
    #pragma unroll
    for (int i = 0; i < HID / 32; i++) {
        int ch = lane + i * 32;
        float v = fmaf(yrow[ch], sa[ch], sc[ch]);
        v = fmaxf(v, 0.f);
        s = fmaf(v, fc3_w[ch], s);
    }
    #pragma unroll
    for (int o = 16; o > 0; o >>= 1)
        s += __shfl_xor_sync(0xFFFFFFFFu, s, o);

    if (lane == 0) {
        float z = s + fc3_b[0];
        out[b] = 1.0f / (1.0f + expf(-z));
    }
}

// =====================================================================
// Launch
// =====================================================================
extern "C" void kernel_launch(void* const* d_in, const int* in_sizes, int n_in,
                              void* d_out, int out_size)
{
    const float* uf     = (const float*)d_in[1];
    const int*   ul     = (const int*)  d_in[2];
    const float* hf     = (const float*)d_in[3];
    const int*   hl     = (const int*)  d_in[4];
    const int*   users  = (const int*)  d_in[5];
    const int*   items  = (const int*)  d_in[6];
    const float* fc1_w  = (const float*)d_in[7];
    const float* fc1_b  = (const float*)d_in[8];
    const float* gamma  = (const float*)d_in[9];
    const float* beta   = (const float*)d_in[10];
    const float* fc3_w  = (const float*)d_in[11];
    const float* fc3_b  = (const float*)d_in[12];
    const float* u_mf   = (const float*)d_in[13];
    const float* i_mf   = (const float*)d_in[14];
    const float* u_mlp  = (const float*)d_in[15];
    const float* i_mlp  = (const float*)d_in[16];
    const float* w0     = (const float*)d_in[17];
    const float* b0     = (const float*)d_in[18];
    const float* w1     = (const float*)d_in[19];
    const float* b1     = (const float*)d_in[20];
    const float* w2     = (const float*)d_in[21];
    const float* b2     = (const float*)d_in[22];
    float* out = (float*)d_out;

    masked_mean_kernel<<<dim3(B_SZ, 2), 192>>>(uf, ul, hf, hl);
    ncf_kernel<<<8, 128>>>(users, items, u_mf, i_mf, u_mlp, i_mlp,
                           w0, b0, w1, b1, w2, b2);
    fc1_gemm_kernel<<<dim3(32, 4, 4), 64>>>(fc1_w);
    bn_combine_kernel<<<128, 512>>>(fc1_b);
    final_kernel<<<128, 256>>>(gamma, beta, fc3_w, fc3_b, out);
}

// round 12
// speedup vs baseline: 1.3097x; 1.3097x over previous
#include <cuda_runtime.h>
#include <cuda_bf16.h>
#include <math.h>

// Problem constants
#define B_SZ   1024
#define LU     200
#define LH     50
#define D_SZ   768
#define XCOLS  1552      // 768 + 768 + 16
#define HID    512

// -------- scratch (device globals; no allocation allowed) --------
__device__ __align__(16) float g_x[B_SZ * XCOLS];     // concatenated input to fc1
__device__ __align__(16) float g_y[B_SZ * HID];       // fc1 output (pre-BN)
__device__ __align__(16) float g_p[4][B_SZ * HID];    // GEMM partials (split-K=4)
__device__ float g_sum[HID];                          // column sums
__device__ float g_sum2[HID];                         // column sums of squares

// =====================================================================
// Kernel 1: masked mean over [B, L, 768] -> g_x columns [off, off+768)
// grid: (1024, 2)  block: 192 threads (192 * float4 = 768 cols)
// =====================================================================
__global__ void masked_mean_kernel(const float* __restrict__ uf,
                                   const int*   __restrict__ ul,
                                   const float* __restrict__ hf,
                                   const int*   __restrict__ hl)
{
    int b = blockIdx.x;
    int t = threadIdx.x;

    const float4* base;
    int len, off;
    if (blockIdx.y == 0) {
        base = (const float4*)(uf + (size_t)b * LU * D_SZ);
        len  = ul[b];
        off  = 0;
    } else {
        base = (const float4*)(hf + (size_t)b * LH * D_SZ);
        len  = hl[b];
        off  = 768;
    }

    float4 s0 = make_float4(0.f, 0.f, 0.f, 0.f);
    float4 s1 = s0, s2 = s0, s3 = s0;

    int l = 0;
    for (; l + 4 <= len; l += 4) {
        float4 v0 = base[(size_t)(l + 0) * 192 + t];
        float4 v1 = base[(size_t)(l + 1) * 192 + t];
        float4 v2 = base[(size_t)(l + 2) * 192 + t];
        float4 v3 = base[(size_t)(l + 3) * 192 + t];
        s0.x += v0.x; s0.y += v0.y; s0.z += v0.z; s0.w += v0.w;
        s1.x += v1.x; s1.y += v1.y; s1.z += v1.z; s1.w += v1.w;
        s2.x += v2.x; s2.y += v2.y; s2.z += v2.z; s2.w += v2.w;
        s3.x += v3.x; s3.y += v3.y; s3.z += v3.z; s3.w += v3.w;
    }
    for (; l < len; l++) {
        float4 v = base[(size_t)l * 192 + t];
        s0.x += v.x; s0.y += v.y; s0.z += v.z; s0.w += v.w;
    }

    float inv = 1.0f / (float)len;
    float4 r;
    r.x = ((s0.x + s1.x) + (s2.x + s3.x)) * inv;
    r.y = ((s0.y + s1.y) + (s2.y + s3.y)) * inv;
    r.z = ((s0.z + s1.z) + (s2.z + s3.z)) * inv;
    r.w = ((s0.w + s1.w) + (s2.w + s3.w)) * inv;

    *(float4*)(g_x + (size_t)b * XCOLS + off + t * 4) = r;
}

// =====================================================================
// Kernel 2: NeuMF interaction vector -> g_x columns [1536, 1552)
// Also zeroes g_sum / g_sum2 for this replay (block 0).
// grid: 8 blocks x 128 threads (1 thread per batch row)
// =====================================================================
__global__ void ncf_kernel(const int* __restrict__ users, const int* __restrict__ items,
                           const float* __restrict__ u_mf,  const float* __restrict__ i_mf,
                           const float* __restrict__ u_mlp, const float* __restrict__ i_mlp,
                           const float* __restrict__ w0, const float* __restrict__ b0,
                           const float* __restrict__ w1, const float* __restrict__ b1,
                           const float* __restrict__ w2, const float* __restrict__ b2)
{
    __shared__ float sw0[16 * 32], sb0[32];
    __shared__ float sw1[32 * 16], sb1[16];
    __shared__ float sw2[16 * 8],  sb2[8];

    int t = threadIdx.x;

    if (blockIdx.x == 0) {
        #pragma unroll
        for (int i = 0; i < 4; i++) {
            g_sum [t + i * 128] = 0.f;
            g_sum2[t + i * 128] = 0.f;
        }
    }

    for (int i = t; i < 512; i += 128) sw0[i] = w0[i];
    for (int i = t; i < 512; i += 128) sw1[i] = w1[i];
    if (t < 128) sw2[t] = w2[t];
    if (t < 32)  sb0[t] = b0[t];
    if (t < 16)  sb1[t] = b1[t];
    if (t < 8)   sb2[t] = b2[t];
    __syncthreads();

    int b = blockIdx.x * 128 + t;
    int u = users[b];
    int it = items[b];

    float in16[16];
    #pragma unroll
    for (int j = 0; j < 8; j++) in16[j]     = u_mlp[u * 8 + j];
    #pragma unroll
    for (int j = 0; j < 8; j++) in16[8 + j] = i_mlp[it * 8 + j];

    float h1[32];
    #pragma unroll
    for (int j = 0; j < 32; j++) {
        float s = sb0[j];
        #pragma unroll
        for (int k = 0; k < 16; k++) s += in16[k] * sw0[k * 32 + j];
        h1[j] = fmaxf(s, 0.f);
    }
    float h2[16];
    #pragma unroll
    for (int j = 0; j < 16; j++) {
        float s = sb1[j];
        #pragma unroll
        for (int k = 0; k < 32; k++) s += h1[k] * sw1[k * 16 + j];
        h2[j] = fmaxf(s, 0.f);
    }
    float* xp = g_x + (size_t)b * XCOLS + 1536;
    #pragma unroll
    for (int j = 0; j < 8; j++) {
        float s = sb2[j];
        #pragma unroll
        for (int k = 0; k < 16; k++) s += h2[k] * sw2[k * 8 + j];
        xp[j] = fmaxf(s, 0.f);
    }
    #pragma unroll
    for (int j = 0; j < 8; j++) {
        xp[8 + j] = u_mf[u * 8 + j] * i_mf[it * 8 + j];
    }
}

// =====================================================================
// Kernel 3: fc1 GEMM, split-K=4 with BK=8.
//   K splits: z*384, tiles = 48 for z<3, 50 for z==3 (384+384+384+400=1552)
// Block tile 32(M) x 128(N), BK=8, 64 threads, 8x8 micro-tile.
// grid: (32, 4, 4) = 1024 blocks x 2 warps = 3.46 warps/SMSP.
// =====================================================================
__global__ void __launch_bounds__(64) fc1_gemm_kernel(const float* __restrict__ W)
{
    __shared__ __align__(16) float As[8][36];   // [k][m], padded row (144B)
    __shared__ __align__(16) float Bs[8][128];  // [k][n]

    int t  = threadIdx.x;
    int m0 = blockIdx.x * 32;
    int n0 = blockIdx.y * 128;
    int z  = blockIdx.z;
    int k0 = z * 384;
    int nkt = (z == 3) ? 50 : 48;

    // A loaders: row a_r (0..31), k-quad a_k (0 or 4)
    int a_r = t >> 1;
    int a_k = (t & 1) * 4;
    // B loaders: row b_k (0..3) + b_k+4, cols b_n and b_n+64
    int b_k = t >> 4;             // 0..3
    int b_n = (t & 15) * 4;       // 0..60

    const float* gA = g_x + (size_t)(m0 + a_r) * XCOLS + k0 + a_k;
    const float* gB = W + (size_t)(k0 + b_k) * HID + n0 + b_n;

    float4 pa  = *(const float4*)gA;
    float4 pb0 = *(const float4*)gB;
    float4 pb1 = *(const float4*)(gB + 64);
    float4 pb2 = *(const float4*)(gB + 4 * HID);
    float4 pb3 = *(const float4*)(gB + 4 * HID + 64);

    int tm = t & 3;   // row group: rows tm*8 .. tm*8+7
    int tn = t >> 2;  // col group: cols tn*8 .. tn*8+7  (0..15)

    unsigned long long acc[8][4] = {};  // [m][n-pair] packed f32x2

    for (int kt = 0; kt < nkt; kt++) {
        __syncthreads();
        As[a_k + 0][a_r] = pa.x;
        As[a_k + 1][a_r] = pa.y;
        As[a_k + 2][a_r] = pa.z;
        As[a_k + 3][a_r] = pa.w;
        *(float4*)&Bs[b_k    ][b_n]      = pb0;
        *(float4*)&Bs[b_k    ][b_n + 64] = pb1;
        *(float4*)&Bs[b_k + 4][b_n]      = pb2;
        *(float4*)&Bs[b_k + 4][b_n + 64] = pb3;
        __syncthreads();

        if (kt + 1 < nkt) {
            const float* nA = gA + (size_t)(kt + 1) * 8;
            const float* nB = gB + (size_t)(kt + 1) * 8 * HID;
            pa  = *(const float4*)nA;
            pb0 = *(const float4*)nB;
            pb1 = *(const float4*)(nB + 64);
            pb2 = *(const float4*)(nB + 4 * HID);
            pb3 = *(const float4*)(nB + 4 * HID + 64);
        }

        #pragma unroll
        for (int k = 0; k < 8; k++) {
            ulonglong2 b01 = *(const ulonglong2*)&Bs[k][tn * 8];
            ulonglong2 b23 = *(const ulonglong2*)&Bs[k][tn * 8 + 4];
            float4 a0 = *(const float4*)&As[k][tm * 8];
            float4 a1 = *(const float4*)&As[k][tm * 8 + 4];
            float am[8] = {a0.x, a0.y, a0.z, a0.w, a1.x, a1.y, a1.z, a1.w};
            #pragma unroll
            for (int m = 0; m < 8; m++) {
                unsigned int av = __float_as_uint(am[m]);
                unsigned long long ad;
                asm("mov.b64 %0, {%1, %1};" : "=l"(ad) : "r"(av));
                asm("fma.rn.f32x2 %0, %1, %2, %0;" : "+l"(acc[m][0]) : "l"(ad), "l"(b01.x));
                asm("fma.rn.f32x2 %0, %1, %2, %0;" : "+l"(acc[m][1]) : "l"(ad), "l"(b01.y));
                asm("fma.rn.f32x2 %0, %1, %2, %0;" : "+l"(acc[m][2]) : "l"(ad), "l"(b23.x));
                asm("fma.rn.f32x2 %0, %1, %2, %0;" : "+l"(acc[m][3]) : "l"(ad), "l"(b23.y));
            }
        }
    }

    float* outp = g_p[z];
    #pragma unroll
    for (int m = 0; m < 8; m++) {
        int row = m0 + tm * 8 + m;
        int col = n0 + tn * 8;
        float4 v0, v1;
        v0.x = __uint_as_float((unsigned int)(acc[m][0]));
        v0.y = __uint_as_float((unsigned int)(acc[m][0] >> 32));
        v0.z = __uint_as_float((unsigned int)(acc[m][1]));
        v0.w = __uint_as_float((unsigned int)(acc[m][1] >> 32));
        v1.x = __uint_as_float((unsigned int)(acc[m][2]));
        v1.y = __uint_as_float((unsigned int)(acc[m][2] >> 32));
        v1.z = __uint_as_float((unsigned int)(acc[m][3]));
        v1.w = __uint_as_float((unsigned int)(acc[m][3] >> 32));
        *(float4*)(outp + (size_t)row * HID + col)     = v0;
        *(float4*)(outp + (size_t)row * HID + col + 4) = v1;
    }
}

// =====================================================================
// Kernel 4: combine split-K partials + bias, write g_y, accumulate
// per-column sums for BN (atomics; zeroed in ncf_kernel).
// grid: 128 blocks x 512 threads (thread = column), 8 rows per block
// =====================================================================
__global__ void bn_combine_kernel(const float* __restrict__ bias)
{
    int c  = threadIdx.x;
    int r0 = blockIdx.x * 8;
    float bs = bias[c];

    float s = 0.f, s2 = 0.f;
    #pragma unroll
    for (int i = 0; i < 8; i++) {
        size_t idx = (size_t)(r0 + i) * HID + c;
        float v = ((g_p[0][idx] + g_p[1][idx]) + (g_p[2][idx] + g_p[3][idx])) + bs;
        g_y[idx] = v;
        s  += v;
        s2 += v * v;
    }
    atomicAdd(&g_sum[c],  s);
    atomicAdd(&g_sum2[c], s2);
}

// =====================================================================
// Kernel 5: out[b] = sigmoid( relu(y*a + c) . fc3_w + fc3_b )
// Per-block: compute BN affine (a,c) into smem from g_sum/g_sum2,
// then 1 warp per batch row.
// grid: 128 blocks x 256 threads
// =====================================================================
__global__ void final_kernel(const float* __restrict__ gamma,
                             const float* __restrict__ beta,
                             const float* __restrict__ fc3_w,
                             const float* __restrict__ fc3_b,
                             float* __restrict__ out)
{
    __shared__ float sa[HID];
    __shared__ float sc[HID];

    int t = threadIdx.x;
    #pragma unroll
    for (int i = 0; i < 2; i++) {
        int ch = t + i * 256;
        float s1 = g_sum[ch];
        float s2 = g_sum2[ch];
        float m   = s1 * (1.0f / (float)B_SZ);
        float var = s2 * (1.0f / (float)B_SZ) - m * m;
        float a   = gamma[ch] * rsqrtf(var + 1e-5f);
        sa[ch] = a;
        sc[ch] = beta[ch] - m * a;
    }
    __syncthreads();

    int warp = t >> 5;
    int lane = t & 31;
    int b = blockIdx.x * 8 + warp;

    const float* yrow = g_y + (size_t)b * HID;
    float s = 0.f;
    #pragma unroll
    for (int i = 0; i < HID / 32; i++) {
        int ch = lane + i * 32;
        float v = fmaf(yrow[ch], sa[ch], sc[ch]);
        v = fmaxf(v, 0.f);
        s = fmaf(v, fc3_w[ch], s);
    }
    #pragma unroll
    for (int o = 16; o > 0; o >>= 1)
        s += __shfl_xor_sync(0xFFFFFFFFu, s, o);

    if (lane == 0) {
        float z = s + fc3_b[0];
        out[b] = 1.0f / (1.0f + expf(-z));
    }
}

// =====================================================================
// Launch
// =====================================================================
extern "C" void kernel_launch(void* const* d_in, const int* in_sizes, int n_in,
                              void* d_out, int out_size)
{
    const float* uf     = (const float*)d_in[1];
    const int*   ul     = (const int*)  d_in[2];
    const float* hf     = (const float*)d_in[3];
    const int*   hl     = (const int*)  d_in[4];
    const int*   users  = (const int*)  d_in[5];
    const int*   items  = (const int*)  d_in[6];
    const float* fc1_w  = (const float*)d_in[7];
    const float* fc1_b  = (const float*)d_in[8];
    const float* gamma  = (const float*)d_in[9];
    const float* beta   = (const float*)d_in[10];
    const float* fc3_w  = (const float*)d_in[11];
    const float* fc3_b  = (const float*)d_in[12];
    const float* u_mf   = (const float*)d_in[13];
    const float* i_mf   = (const float*)d_in[14];
    const float* u_mlp  = (const float*)d_in[15];
    const float* i_mlp  = (const float*)d_in[16];
    const float* w0     = (const float*)d_in[17];
    const float* b0     = (const float*)d_in[18];
    const float* w1     = (const float*)d_in[19];
    const float* b1     = (const float*)d_in[20];
    const float* w2     = (const float*)d_in[21];
    const float* b2     = (const float*)d_in[22];
    float* out = (float*)d_out;

    masked_mean_kernel<<<dim3(B_SZ, 2), 192>>>(uf, ul, hf, hl);
    ncf_kernel<<<8, 128>>>(users, items, u_mf, i_mf, u_mlp, i_mlp,
                           w0, b0, w1, b1, w2, b2);
    fc1_gemm_kernel<<<dim3(32, 4, 4), 64>>>(fc1_w);
    bn_combine_kernel<<<128, 512>>>(fc1_b);
    final_kernel<<<128, 256>>>(gamma, beta, fc3_w, fc3_b, out);
}